// round 1
// baseline (speedup 1.0000x reference)
#include <cuda_runtime.h>
#include <cstdint>

// Problem constants
#define B_ 2
#define S_ 2048
#define E_ 2048
#define H_ 16
#define D_ 128
#define MROWS (B_ * S_)   // 4096

// Scratch (no cudaMalloc allowed) — 4 x 32MB fp32
__device__ float g_Q[(size_t)B_ * S_ * E_];
__device__ float g_K[(size_t)B_ * S_ * E_];
__device__ float g_V[(size_t)B_ * S_ * E_];
__device__ float g_C[(size_t)B_ * S_ * E_];

// ---------------------------------------------------------------------------
// SGEMM:  C[M,N] = A[M,K] * W[K,N] + bias[N]
// 128x128 block tile, BK=8, 8x8 per thread, 256 threads.
// Assumes M%128==0, N%128==0, K%8==0 (true here: 4096/2048/2048).
// ---------------------------------------------------------------------------
__global__ void __launch_bounds__(256) sgemm_bias_kernel(
    const float* __restrict__ A, const float* __restrict__ W,
    const float* __restrict__ bias, float* __restrict__ C,
    int M, int N, int K)
{
    __shared__ float As[8][128];   // transposed A tile: As[k][m]
    __shared__ float Bs[8][128];   // Bs[k][n]

    const int bx = blockIdx.x;     // N tile
    const int by = blockIdx.y;     // M tile
    const int tid = threadIdx.x;
    const int tx = tid & 15;       // 0..15 -> N
    const int ty = tid >> 4;       // 0..15 -> M

    const int aRow = tid >> 1;           // 0..127
    const int aCol = (tid & 1) * 4;      // 0 or 4
    const int bRow = tid >> 5;           // 0..7
    const int bCol = (tid & 31) * 4;     // 0..124

    const float* Aptr = A + (size_t)(by * 128 + aRow) * K + aCol;
    const float* Wptr = W + (size_t)bRow * N + bx * 128 + bCol;

    float acc[8][8];
    #pragma unroll
    for (int i = 0; i < 8; ++i)
        #pragma unroll
        for (int j = 0; j < 8; ++j) acc[i][j] = 0.f;

    for (int k0 = 0; k0 < K; k0 += 8) {
        float4 av = *(const float4*)(Aptr + k0);
        As[aCol + 0][aRow] = av.x;
        As[aCol + 1][aRow] = av.y;
        As[aCol + 2][aRow] = av.z;
        As[aCol + 3][aRow] = av.w;
        float4 bv = *(const float4*)(Wptr + (size_t)k0 * N);
        *(float4*)&Bs[bRow][bCol] = bv;
        __syncthreads();

        #pragma unroll
        for (int k = 0; k < 8; ++k) {
            float a[8], b[8];
            float4 a0 = *(const float4*)&As[k][ty * 8];
            float4 a1 = *(const float4*)&As[k][ty * 8 + 4];
            a[0]=a0.x; a[1]=a0.y; a[2]=a0.z; a[3]=a0.w;
            a[4]=a1.x; a[5]=a1.y; a[6]=a1.z; a[7]=a1.w;
            float4 b0 = *(const float4*)&Bs[k][tx * 8];
            float4 b1 = *(const float4*)&Bs[k][tx * 8 + 4];
            b[0]=b0.x; b[1]=b0.y; b[2]=b0.z; b[3]=b0.w;
            b[4]=b1.x; b[5]=b1.y; b[6]=b1.z; b[7]=b1.w;
            #pragma unroll
            for (int i = 0; i < 8; ++i)
                #pragma unroll
                for (int j = 0; j < 8; ++j)
                    acc[i][j] = fmaf(a[i], b[j], acc[i][j]);
        }
        __syncthreads();
    }

    // epilogue with bias
    #pragma unroll
    for (int i = 0; i < 8; ++i) {
        const size_t crow = (size_t)(by * 128 + ty * 8 + i) * N + bx * 128 + tx * 8;
        float4 o0, o1;
        const float* bp = bias + bx * 128 + tx * 8;
        o0.x = acc[i][0] + bp[0]; o0.y = acc[i][1] + bp[1];
        o0.z = acc[i][2] + bp[2]; o0.w = acc[i][3] + bp[3];
        o1.x = acc[i][4] + bp[4]; o1.y = acc[i][5] + bp[5];
        o1.z = acc[i][6] + bp[6]; o1.w = acc[i][7] + bp[7];
        *(float4*)(C + crow)     = o0;
        *(float4*)(C + crow + 4) = o1;
    }
}

// ---------------------------------------------------------------------------
// Flash attention (fp32, online softmax).
// Grid: (S/64, H, B). Block: 256 threads (16x16).
// Each block: 64 query rows of one head. Iterates over 32 kv-tiles of 64.
// ---------------------------------------------------------------------------
#define FL_SMEM_FLOATS (128*64 + 128*64 + 64*128 + 64*64 + 64*4 + 64*3)
#define FL_SMEM_BYTES  (FL_SMEM_FLOATS * 4)

__global__ void __launch_bounds__(256) flash_attn_kernel(
    const float* __restrict__ Q, const float* __restrict__ Kg,
    const float* __restrict__ Vg, float* __restrict__ Ctx)
{
    extern __shared__ float sm[];
    float* Qt = sm;                 // [128][64]  (d-major)
    float* Kt = Qt + 128 * 64;      // [128][64]  (d-major)
    float* Vs = Kt + 128 * 64;      // [64][128]  (row-major)
    float* Ss = Vs + 64 * 128;      // [64][64]
    float* rowPart = Ss + 64 * 64;  // [64][4]
    float* rowM = rowPart + 256;    // [64]
    float* rowL = rowM + 64;        // [64]
    float* rowA = rowL + 64;        // [64]

    const int qt = blockIdx.x;
    const int h  = blockIdx.y;
    const int b  = blockIdx.z;
    const int tid = threadIdx.x;
    const int tx = tid & 15;
    const int ty = tid >> 4;
    const float scale = 0.08838834764831845f;  // 1/sqrt(128)

    const float* Qbase = Q + ((size_t)b * S_ + qt * 64) * E_ + h * D_;

    // Load Q tile transposed: Qt[d][row]
    for (int i = tid; i < 64 * 32; i += 256) {
        int row = i >> 5;
        int c4  = (i & 31) * 4;
        float4 v = *(const float4*)(Qbase + (size_t)row * E_ + c4);
        Qt[(c4 + 0) * 64 + row] = v.x;
        Qt[(c4 + 1) * 64 + row] = v.y;
        Qt[(c4 + 2) * 64 + row] = v.z;
        Qt[(c4 + 3) * 64 + row] = v.w;
    }
    if (tid < 64) { rowM[tid] = -1e30f; rowL[tid] = 0.f; }

    float acc[4][8];
    #pragma unroll
    for (int r = 0; r < 4; ++r)
        #pragma unroll
        for (int c = 0; c < 8; ++c) acc[r][c] = 0.f;

    for (int kt = 0; kt < S_ / 64; ++kt) {
        __syncthreads();   // protects Kt/Vs reuse + Q/stats visibility (iter 0)

        const float* Kbase = Kg + ((size_t)b * S_ + kt * 64) * E_ + h * D_;
        const float* Vbase = Vg + ((size_t)b * S_ + kt * 64) * E_ + h * D_;
        for (int i = tid; i < 64 * 32; i += 256) {
            int row = i >> 5;
            int c4  = (i & 31) * 4;
            float4 v = *(const float4*)(Kbase + (size_t)row * E_ + c4);
            Kt[(c4 + 0) * 64 + row] = v.x;
            Kt[(c4 + 1) * 64 + row] = v.y;
            Kt[(c4 + 2) * 64 + row] = v.z;
            Kt[(c4 + 3) * 64 + row] = v.w;
            float4 w = *(const float4*)(Vbase + (size_t)row * E_ + c4);
            *(float4*)(Vs + row * 128 + c4) = w;
        }
        __syncthreads();

        // S = (Q K^T) * scale  -> Ss
        float s4[4][4];
        #pragma unroll
        for (int r = 0; r < 4; ++r)
            #pragma unroll
            for (int c = 0; c < 4; ++c) s4[r][c] = 0.f;

        for (int d = 0; d < 128; ++d) {
            float qv[4], kv[4];
            #pragma unroll
            for (int r = 0; r < 4; ++r) qv[r] = Qt[d * 64 + ty * 4 + r];
            #pragma unroll
            for (int c = 0; c < 4; ++c) kv[c] = Kt[d * 64 + tx * 4 + c];
            #pragma unroll
            for (int r = 0; r < 4; ++r)
                #pragma unroll
                for (int c = 0; c < 4; ++c)
                    s4[r][c] = fmaf(qv[r], kv[c], s4[r][c]);
        }
        #pragma unroll
        for (int r = 0; r < 4; ++r)
            #pragma unroll
            for (int c = 0; c < 4; ++c)
                Ss[(ty * 4 + r) * 64 + tx * 4 + c] = s4[r][c] * scale;
        __syncthreads();

        // partial row max (4 threads per row, 16 elems each)
        {
            int row = tid >> 2, p = tid & 3;
            float m = -1e30f;
            #pragma unroll
            for (int j = 0; j < 16; ++j) m = fmaxf(m, Ss[row * 64 + p * 16 + j]);
            rowPart[row * 4 + p] = m;
        }
        __syncthreads();
        if (tid < 64) {
            float mo = rowM[tid];
            float nm = fmaxf(fmaxf(rowPart[tid * 4], rowPart[tid * 4 + 1]),
                             fmaxf(rowPart[tid * 4 + 2], rowPart[tid * 4 + 3]));
            nm = fmaxf(mo, nm);
            float a = __expf(mo - nm);
            rowA[tid] = a;
            rowM[tid] = nm;
            rowL[tid] *= a;
        }
        __syncthreads();

        // exponentiate + partial row sums
        {
            int row = tid >> 2, p = tid & 3;
            float mrow = rowM[row];
            float ssum = 0.f;
            #pragma unroll
            for (int j = 0; j < 16; ++j) {
                float e = __expf(Ss[row * 64 + p * 16 + j] - mrow);
                Ss[row * 64 + p * 16 + j] = e;
                ssum += e;
            }
            rowPart[row * 4 + p] = ssum;
        }
        __syncthreads();
        if (tid < 64) {
            rowL[tid] += rowPart[tid * 4] + rowPart[tid * 4 + 1] +
                         rowPart[tid * 4 + 2] + rowPart[tid * 4 + 3];
        }

        // rescale accumulators by alpha, then accumulate P * V
        float ar[4];
        #pragma unroll
        for (int r = 0; r < 4; ++r) ar[r] = rowA[ty * 4 + r];
        #pragma unroll
        for (int r = 0; r < 4; ++r)
            #pragma unroll
            for (int c = 0; c < 8; ++c) acc[r][c] *= ar[r];

        for (int j = 0; j < 64; ++j) {
            float pr[4];
            #pragma unroll
            for (int r = 0; r < 4; ++r) pr[r] = Ss[(ty * 4 + r) * 64 + j];
            float4 v0 = *(const float4*)(Vs + j * 128 + tx * 8);
            float4 v1 = *(const float4*)(Vs + j * 128 + tx * 8 + 4);
            #pragma unroll
            for (int r = 0; r < 4; ++r) {
                acc[r][0] = fmaf(pr[r], v0.x, acc[r][0]);
                acc[r][1] = fmaf(pr[r], v0.y, acc[r][1]);
                acc[r][2] = fmaf(pr[r], v0.z, acc[r][2]);
                acc[r][3] = fmaf(pr[r], v0.w, acc[r][3]);
                acc[r][4] = fmaf(pr[r], v1.x, acc[r][4]);
                acc[r][5] = fmaf(pr[r], v1.y, acc[r][5]);
                acc[r][6] = fmaf(pr[r], v1.z, acc[r][6]);
                acc[r][7] = fmaf(pr[r], v1.w, acc[r][7]);
            }
        }
    }
    __syncthreads();

    // finalize: divide by l, write Ctx
    #pragma unroll
    for (int r = 0; r < 4; ++r) {
        int row = ty * 4 + r;
        float inv = 1.f / rowL[row];
        float* op = Ctx + ((size_t)b * S_ + qt * 64 + row) * E_ + h * D_ + tx * 8;
        float4 o0, o1;
        o0.x = acc[r][0] * inv; o0.y = acc[r][1] * inv;
        o0.z = acc[r][2] * inv; o0.w = acc[r][3] * inv;
        o1.x = acc[r][4] * inv; o1.y = acc[r][5] * inv;
        o1.z = acc[r][6] * inv; o1.w = acc[r][7] * inv;
        *(float4*)(op)     = o0;
        *(float4*)(op + 4) = o1;
    }
}

// ---------------------------------------------------------------------------
extern "C" void kernel_launch(void* const* d_in, const int* in_sizes, int n_in,
                              void* d_out, int out_size)
{
    const float* query  = (const float*)d_in[0];
    const float* key_in = (const float*)d_in[1];
    const float* value  = (const float*)d_in[2];
    const float* Wq = (const float*)d_in[3];
    const float* bq = (const float*)d_in[4];
    const float* Wk = (const float*)d_in[5];
    const float* bk = (const float*)d_in[6];
    const float* Wv = (const float*)d_in[7];
    const float* bv = (const float*)d_in[8];
    const float* Wo = (const float*)d_in[9];
    const float* bo = (const float*)d_in[10];
    float* out = (float*)d_out;

    float *Qb, *Kb, *Vb, *Cb;
    cudaGetSymbolAddress((void**)&Qb, g_Q);
    cudaGetSymbolAddress((void**)&Kb, g_K);
    cudaGetSymbolAddress((void**)&Vb, g_V);
    cudaGetSymbolAddress((void**)&Cb, g_C);

    cudaFuncSetAttribute(flash_attn_kernel,
                         cudaFuncAttributeMaxDynamicSharedMemorySize,
                         FL_SMEM_BYTES);

    dim3 gg(E_ / 128, MROWS / 128);   // (16, 32)
    sgemm_bias_kernel<<<gg, 256>>>(query,  Wq, bq, Qb, MROWS, E_, E_);
    sgemm_bias_kernel<<<gg, 256>>>(key_in, Wk, bk, Kb, MROWS, E_, E_);
    sgemm_bias_kernel<<<gg, 256>>>(value,  Wv, bv, Vb, MROWS, E_, E_);

    dim3 fg(S_ / 64, H_, B_);         // (32, 16, 2)
    flash_attn_kernel<<<fg, 256, FL_SMEM_BYTES>>>(Qb, Kb, Vb, Cb);

    sgemm_bias_kernel<<<gg, 256>>>(Cb, Wo, bo, out, MROWS, E_, E_);
}

// round 4
// speedup vs baseline: 1.2316x; 1.2316x over previous
#include <cuda_runtime.h>
#include <cuda_bf16.h>
#include <cstdint>

// Problem constants
#define B_ 2
#define S_ 2048
#define E_ 2048
#define H_ 16
#define D_ 128
#define MROWS (B_ * S_)   // 4096

// ---------------------------------------------------------------------------
// Scratch (no cudaMalloc allowed)
// ---------------------------------------------------------------------------
__device__ float g_Q[(size_t)B_ * S_ * E_];
__device__ float g_K[(size_t)B_ * S_ * E_];
__device__ float g_V[(size_t)B_ * S_ * E_];
__device__ float g_C[(size_t)B_ * S_ * E_];
__device__ __nv_bfloat16 g_Ahi[(size_t)MROWS * E_];   // activations split
__device__ __nv_bfloat16 g_Alo[(size_t)MROWS * E_];
__device__ __nv_bfloat16 g_Whi[(size_t)E_ * E_];      // weights split, transposed [N][K]
__device__ __nv_bfloat16 g_Wlo[(size_t)E_ * E_];

// ---------------------------------------------------------------------------
// Helpers: smem address, ldmatrix, mma.sync (all legal on base sm_103 target)
// ---------------------------------------------------------------------------
__device__ __forceinline__ uint32_t smem_u32(const void* p) {
    uint32_t a;
    asm("{ .reg .u64 t; cvta.to.shared.u64 t, %1; cvt.u32.u64 %0, t; }"
        : "=r"(a) : "l"(p));
    return a;
}

__device__ __forceinline__ void ldsm_x4(uint32_t* r, uint32_t addr) {
    asm volatile("ldmatrix.sync.aligned.m8n8.x4.shared.b16 {%0,%1,%2,%3}, [%4];"
        : "=r"(r[0]), "=r"(r[1]), "=r"(r[2]), "=r"(r[3]) : "r"(addr));
}
__device__ __forceinline__ void ldsm_x2(uint32_t* r, uint32_t addr) {
    asm volatile("ldmatrix.sync.aligned.m8n8.x2.shared.b16 {%0,%1}, [%2];"
        : "=r"(r[0]), "=r"(r[1]) : "r"(addr));
}

// D = A(16x16 bf16) * B(16x8 bf16) + D, fp32 accum
__device__ __forceinline__ void mma16816(float* c, const uint32_t* a, const uint32_t* b) {
    asm volatile(
        "mma.sync.aligned.m16n8k16.row.col.f32.bf16.bf16.f32 "
        "{%0,%1,%2,%3}, {%4,%5,%6,%7}, {%8,%9}, {%0,%1,%2,%3};"
        : "+f"(c[0]), "+f"(c[1]), "+f"(c[2]), "+f"(c[3])
        : "r"(a[0]), "r"(a[1]), "r"(a[2]), "r"(a[3]), "r"(b[0]), "r"(b[1]));
}

#define SMEM_SWIZZLE_128B(off) ((off) ^ (((off) >> 3) & 0x70))

// ---------------------------------------------------------------------------
// Split fp32 activations into (hi, lo) bf16, same layout [M][K]
// ---------------------------------------------------------------------------
__global__ void __launch_bounds__(256) splitA_kernel(
    const float* __restrict__ x, __nv_bfloat16* __restrict__ hi,
    __nv_bfloat16* __restrict__ lo)
{
    size_t i = (size_t)blockIdx.x * 256 + threadIdx.x;  // one float4
    float4 v = ((const float4*)x)[i];
    __nv_bfloat16 h0 = __float2bfloat16(v.x);
    __nv_bfloat16 h1 = __float2bfloat16(v.y);
    __nv_bfloat16 h2 = __float2bfloat16(v.z);
    __nv_bfloat16 h3 = __float2bfloat16(v.w);
    __nv_bfloat16 l0 = __float2bfloat16(v.x - __bfloat162float(h0));
    __nv_bfloat16 l1 = __float2bfloat16(v.y - __bfloat162float(h1));
    __nv_bfloat16 l2 = __float2bfloat16(v.z - __bfloat162float(h2));
    __nv_bfloat16 l3 = __float2bfloat16(v.w - __bfloat162float(h3));
    __nv_bfloat162 p;
    __nv_bfloat162* H = (__nv_bfloat162*)hi;
    __nv_bfloat162* L = (__nv_bfloat162*)lo;
    p.x = h0; p.y = h1; H[2 * i]     = p;
    p.x = h2; p.y = h3; H[2 * i + 1] = p;
    p.x = l0; p.y = l1; L[2 * i]     = p;
    p.x = l2; p.y = l3; L[2 * i + 1] = p;
}

// ---------------------------------------------------------------------------
// Transpose + split fp32 weights W[K][N] -> hi/lo bf16 [N][K]
// ---------------------------------------------------------------------------
__global__ void __launch_bounds__(256) convW_kernel(
    const float* __restrict__ W, __nv_bfloat16* __restrict__ hi,
    __nv_bfloat16* __restrict__ lo)
{
    __shared__ float t[32][33];
    int tx = threadIdx.x & 31, ty = threadIdx.x >> 5;  // 32 x 8
    int nb = blockIdx.x * 32, kb = blockIdx.y * 32;
    #pragma unroll
    for (int i = 0; i < 4; ++i) {
        int k = kb + ty + i * 8;
        t[ty + i * 8][tx] = W[(size_t)k * E_ + nb + tx];
    }
    __syncthreads();
    #pragma unroll
    for (int i = 0; i < 4; ++i) {
        int n = nb + ty + i * 8;
        float v = t[tx][ty + i * 8];
        __nv_bfloat16 h = __float2bfloat16(v);
        hi[(size_t)n * E_ + kb + tx] = h;
        lo[(size_t)n * E_ + kb + tx] = __float2bfloat16(v - __bfloat162float(h));
    }
}

// ---------------------------------------------------------------------------
// mma.sync split-bf16 GEMM: C[M,N] = A[M,K] * B[N,K]^T + bias
//   128x128 CTA tile, BK=64, 8 warps (2x4), 64x32 warp tile.
//   D = Ahi*Bhi + Ahi*Blo + Alo*Bhi  (fp32 accumulate)
//   Smem tiles [128 rows][64 bf16] with SW128 swizzle -> conflict-free ldmatrix.
// ---------------------------------------------------------------------------
#define GEMM_SMEM (4 * 16384)

__global__ void __launch_bounds__(256) gemm_mma_kernel(
    const __nv_bfloat16* __restrict__ Ahi, const __nv_bfloat16* __restrict__ Alo,
    const __nv_bfloat16* __restrict__ Bhi, const __nv_bfloat16* __restrict__ Blo,
    const float* __restrict__ bias, float* __restrict__ C)
{
    extern __shared__ char smc[];
    const uint32_t sb  = smem_u32(smc);
    const uint32_t SAH = sb;
    const uint32_t SAL = sb + 16384;
    const uint32_t SBH = sb + 32768;
    const uint32_t SBL = sb + 49152;

    const int tid  = threadIdx.x;
    const int wid  = tid >> 5;
    const int lane = tid & 31;
    const int bx = blockIdx.x;   // N tile (16)
    const int by = blockIdx.y;   // M tile (32)

    const int warpM = (wid >> 2) * 64;   // 0 or 64
    const int warpN = (wid & 3) * 32;    // 0,32,64,96

    const size_t aRow0 = (size_t)by * 128;
    const size_t bRow0 = (size_t)bx * 128;

    float acc[4][4][4];
    #pragma unroll
    for (int mi = 0; mi < 4; ++mi)
        #pragma unroll
        for (int ni = 0; ni < 4; ++ni)
            #pragma unroll
            for (int j = 0; j < 4; ++j) acc[mi][ni][j] = 0.f;

    // Fragment smem coordinates (lane-dependent, k-base added later)
    const uint32_t aRowL = warpM + (lane & 15);
    const uint32_t aColL = (lane >> 4) * 8;
    const uint32_t bRowL = warpN + (lane & 7);
    const uint32_t bColL = ((lane >> 3) & 1) * 8;

    for (int kc = 0; kc < 32; ++kc) {
        const int k0 = kc * 64;
        __syncthreads();   // previous chunk's reads done before overwrite
        // Load 4 tiles of [128][64] bf16 (SW128 swizzle): 16B per thread x 4
        #pragma unroll
        for (int it = 0; it < 4; ++it) {
            int idx = tid + it * 256;   // 0..1023
            int r = idx >> 3;
            int s = idx & 7;
            uint32_t off = SMEM_SWIZZLE_128B((uint32_t)(r * 128 + s * 16));
            const uint4* pah = (const uint4*)(Ahi + (aRow0 + r) * E_ + k0);
            const uint4* pal = (const uint4*)(Alo + (aRow0 + r) * E_ + k0);
            const uint4* pbh = (const uint4*)(Bhi + (bRow0 + r) * E_ + k0);
            const uint4* pbl = (const uint4*)(Blo + (bRow0 + r) * E_ + k0);
            *(uint4*)(smc + off)         = pah[s];
            *(uint4*)(smc + 16384 + off) = pal[s];
            *(uint4*)(smc + 32768 + off) = pbh[s];
            *(uint4*)(smc + 49152 + off) = pbl[s];
        }
        __syncthreads();

        #pragma unroll
        for (int ks = 0; ks < 4; ++ks) {
            const uint32_t kb = ks * 16;
            uint32_t ah[4][4], al[4][4], bh[4][2], bl[4][2];
            #pragma unroll
            for (int mi = 0; mi < 4; ++mi) {
                uint32_t off = (aRowL + mi * 16) * 128 + (kb + aColL) * 2;
                off = SMEM_SWIZZLE_128B(off);
                ldsm_x4(ah[mi], SAH + off);
                ldsm_x4(al[mi], SAL + off);
            }
            #pragma unroll
            for (int ni = 0; ni < 4; ++ni) {
                uint32_t off = (bRowL + ni * 8) * 128 + (kb + bColL) * 2;
                off = SMEM_SWIZZLE_128B(off);
                ldsm_x2(bh[ni], SBH + off);
                ldsm_x2(bl[ni], SBL + off);
            }
            #pragma unroll
            for (int mi = 0; mi < 4; ++mi)
                #pragma unroll
                for (int ni = 0; ni < 4; ++ni) {
                    mma16816(acc[mi][ni], ah[mi], bh[ni]);
                    mma16816(acc[mi][ni], ah[mi], bl[ni]);
                    mma16816(acc[mi][ni], al[mi], bh[ni]);
                }
        }
    }

    // Epilogue: c0,c1 -> (row, col..col+1); c2,c3 -> (row+8, col..col+1)
    const int rQuad = lane >> 2;          // 0..7
    const int cPair = (lane & 3) * 2;     // 0,2,4,6
    #pragma unroll
    for (int mi = 0; mi < 4; ++mi) {
        #pragma unroll
        for (int ni = 0; ni < 4; ++ni) {
            int row = by * 128 + warpM + mi * 16 + rQuad;
            int col = bx * 128 + warpN + ni * 8 + cPair;
            float b0 = bias[col], b1 = bias[col + 1];
            float2 v0 = make_float2(acc[mi][ni][0] + b0, acc[mi][ni][1] + b1);
            float2 v1 = make_float2(acc[mi][ni][2] + b0, acc[mi][ni][3] + b1);
            *(float2*)(C + (size_t)row * E_ + col)       = v0;
            *(float2*)(C + (size_t)(row + 8) * E_ + col) = v1;
        }
    }
}

// ---------------------------------------------------------------------------
// Flash attention (fp32, online softmax) — unchanged from Round 1
// ---------------------------------------------------------------------------
#define FL_SMEM_FLOATS (128*64 + 128*64 + 64*128 + 64*64 + 64*4 + 64*3)
#define FL_SMEM_BYTES  (FL_SMEM_FLOATS * 4)

__global__ void __launch_bounds__(256) flash_attn_kernel(
    const float* __restrict__ Q, const float* __restrict__ Kg,
    const float* __restrict__ Vg, float* __restrict__ Ctx)
{
    extern __shared__ float sm[];
    float* Qt = sm;                 // [128][64]
    float* Kt = Qt + 128 * 64;      // [128][64]
    float* Vs = Kt + 128 * 64;      // [64][128]
    float* Ss = Vs + 64 * 128;      // [64][64]
    float* rowPart = Ss + 64 * 64;  // [64][4]
    float* rowM = rowPart + 256;
    float* rowL = rowM + 64;
    float* rowA = rowL + 64;

    const int qt = blockIdx.x;
    const int h  = blockIdx.y;
    const int b  = blockIdx.z;
    const int tid = threadIdx.x;
    const int tx = tid & 15;
    const int ty = tid >> 4;
    const float scale = 0.08838834764831845f;

    const float* Qbase = Q + ((size_t)b * S_ + qt * 64) * E_ + h * D_;

    for (int i = tid; i < 64 * 32; i += 256) {
        int row = i >> 5;
        int c4  = (i & 31) * 4;
        float4 v = *(const float4*)(Qbase + (size_t)row * E_ + c4);
        Qt[(c4 + 0) * 64 + row] = v.x;
        Qt[(c4 + 1) * 64 + row] = v.y;
        Qt[(c4 + 2) * 64 + row] = v.z;
        Qt[(c4 + 3) * 64 + row] = v.w;
    }
    if (tid < 64) { rowM[tid] = -1e30f; rowL[tid] = 0.f; }

    float acc[4][8];
    #pragma unroll
    for (int r = 0; r < 4; ++r)
        #pragma unroll
        for (int c = 0; c < 8; ++c) acc[r][c] = 0.f;

    for (int kt = 0; kt < S_ / 64; ++kt) {
        __syncthreads();

        const float* Kbase = Kg + ((size_t)b * S_ + kt * 64) * E_ + h * D_;
        const float* Vbase = Vg + ((size_t)b * S_ + kt * 64) * E_ + h * D_;
        for (int i = tid; i < 64 * 32; i += 256) {
            int row = i >> 5;
            int c4  = (i & 31) * 4;
            float4 v = *(const float4*)(Kbase + (size_t)row * E_ + c4);
            Kt[(c4 + 0) * 64 + row] = v.x;
            Kt[(c4 + 1) * 64 + row] = v.y;
            Kt[(c4 + 2) * 64 + row] = v.z;
            Kt[(c4 + 3) * 64 + row] = v.w;
            float4 w = *(const float4*)(Vbase + (size_t)row * E_ + c4);
            *(float4*)(Vs + row * 128 + c4) = w;
        }
        __syncthreads();

        float s4[4][4];
        #pragma unroll
        for (int r = 0; r < 4; ++r)
            #pragma unroll
            for (int c = 0; c < 4; ++c) s4[r][c] = 0.f;

        for (int d = 0; d < 128; ++d) {
            float qv[4], kv[4];
            #pragma unroll
            for (int r = 0; r < 4; ++r) qv[r] = Qt[d * 64 + ty * 4 + r];
            #pragma unroll
            for (int c = 0; c < 4; ++c) kv[c] = Kt[d * 64 + tx * 4 + c];
            #pragma unroll
            for (int r = 0; r < 4; ++r)
                #pragma unroll
                for (int c = 0; c < 4; ++c)
                    s4[r][c] = fmaf(qv[r], kv[c], s4[r][c]);
        }
        #pragma unroll
        for (int r = 0; r < 4; ++r)
            #pragma unroll
            for (int c = 0; c < 4; ++c)
                Ss[(ty * 4 + r) * 64 + tx * 4 + c] = s4[r][c] * scale;
        __syncthreads();

        {
            int row = tid >> 2, p = tid & 3;
            float m = -1e30f;
            #pragma unroll
            for (int j = 0; j < 16; ++j) m = fmaxf(m, Ss[row * 64 + p * 16 + j]);
            rowPart[row * 4 + p] = m;
        }
        __syncthreads();
        if (tid < 64) {
            float mo = rowM[tid];
            float nm = fmaxf(fmaxf(rowPart[tid * 4], rowPart[tid * 4 + 1]),
                             fmaxf(rowPart[tid * 4 + 2], rowPart[tid * 4 + 3]));
            nm = fmaxf(mo, nm);
            float a = __expf(mo - nm);
            rowA[tid] = a;
            rowM[tid] = nm;
            rowL[tid] *= a;
        }
        __syncthreads();

        {
            int row = tid >> 2, p = tid & 3;
            float mrow = rowM[row];
            float ssum = 0.f;
            #pragma unroll
            for (int j = 0; j < 16; ++j) {
                float e = __expf(Ss[row * 64 + p * 16 + j] - mrow);
                Ss[row * 64 + p * 16 + j] = e;
                ssum += e;
            }
            rowPart[row * 4 + p] = ssum;
        }
        __syncthreads();
        if (tid < 64) {
            rowL[tid] += rowPart[tid * 4] + rowPart[tid * 4 + 1] +
                         rowPart[tid * 4 + 2] + rowPart[tid * 4 + 3];
        }

        float ar[4];
        #pragma unroll
        for (int r = 0; r < 4; ++r) ar[r] = rowA[ty * 4 + r];
        #pragma unroll
        for (int r = 0; r < 4; ++r)
            #pragma unroll
            for (int c = 0; c < 8; ++c) acc[r][c] *= ar[r];

        for (int j = 0; j < 64; ++j) {
            float pr[4];
            #pragma unroll
            for (int r = 0; r < 4; ++r) pr[r] = Ss[(ty * 4 + r) * 64 + j];
            float4 v0 = *(const float4*)(Vs + j * 128 + tx * 8);
            float4 v1 = *(const float4*)(Vs + j * 128 + tx * 8 + 4);
            #pragma unroll
            for (int r = 0; r < 4; ++r) {
                acc[r][0] = fmaf(pr[r], v0.x, acc[r][0]);
                acc[r][1] = fmaf(pr[r], v0.y, acc[r][1]);
                acc[r][2] = fmaf(pr[r], v0.z, acc[r][2]);
                acc[r][3] = fmaf(pr[r], v0.w, acc[r][3]);
                acc[r][4] = fmaf(pr[r], v1.x, acc[r][4]);
                acc[r][5] = fmaf(pr[r], v1.y, acc[r][5]);
                acc[r][6] = fmaf(pr[r], v1.z, acc[r][6]);
                acc[r][7] = fmaf(pr[r], v1.w, acc[r][7]);
            }
        }
    }
    __syncthreads();

    #pragma unroll
    for (int r = 0; r < 4; ++r) {
        int row = ty * 4 + r;
        float inv = 1.f / rowL[row];
        float* op = Ctx + ((size_t)b * S_ + qt * 64 + row) * E_ + h * D_ + tx * 8;
        float4 o0, o1;
        o0.x = acc[r][0] * inv; o0.y = acc[r][1] * inv;
        o0.z = acc[r][2] * inv; o0.w = acc[r][3] * inv;
        o1.x = acc[r][4] * inv; o1.y = acc[r][5] * inv;
        o1.z = acc[r][6] * inv; o1.w = acc[r][7] * inv;
        *(float4*)(op)     = o0;
        *(float4*)(op + 4) = o1;
    }
}

// ---------------------------------------------------------------------------
extern "C" void kernel_launch(void* const* d_in, const int* in_sizes, int n_in,
                              void* d_out, int out_size)
{
    const float* query  = (const float*)d_in[0];
    const float* key_in = (const float*)d_in[1];
    const float* value  = (const float*)d_in[2];
    const float* Wq = (const float*)d_in[3];
    const float* bq = (const float*)d_in[4];
    const float* Wk = (const float*)d_in[5];
    const float* bk = (const float*)d_in[6];
    const float* Wv = (const float*)d_in[7];
    const float* bv = (const float*)d_in[8];
    const float* Wo = (const float*)d_in[9];
    const float* bo = (const float*)d_in[10];
    float* out = (float*)d_out;

    float *Qb, *Kb, *Vb, *Cb;
    __nv_bfloat16 *Ahi, *Alo, *Whi, *Wlo;
    cudaGetSymbolAddress((void**)&Qb, g_Q);
    cudaGetSymbolAddress((void**)&Kb, g_K);
    cudaGetSymbolAddress((void**)&Vb, g_V);
    cudaGetSymbolAddress((void**)&Cb, g_C);
    cudaGetSymbolAddress((void**)&Ahi, g_Ahi);
    cudaGetSymbolAddress((void**)&Alo, g_Alo);
    cudaGetSymbolAddress((void**)&Whi, g_Whi);
    cudaGetSymbolAddress((void**)&Wlo, g_Wlo);

    cudaFuncSetAttribute(flash_attn_kernel,
                         cudaFuncAttributeMaxDynamicSharedMemorySize,
                         FL_SMEM_BYTES);
    cudaFuncSetAttribute(gemm_mma_kernel,
                         cudaFuncAttributeMaxDynamicSharedMemorySize,
                         GEMM_SMEM);

    const dim3 cw(E_ / 32, E_ / 32);            // convW tiles
    const int  sa = (MROWS * E_ / 4) / 256;     // splitA blocks (8192)
    const dim3 gg(E_ / 128, MROWS / 128);       // gemm tiles (16, 32)
    const dim3 fg(S_ / 64, H_, B_);             // flash (32, 16, 2)

    // Q projection
    convW_kernel<<<cw, 256>>>(Wq, Whi, Wlo);
    splitA_kernel<<<sa, 256>>>(query, Ahi, Alo);
    gemm_mma_kernel<<<gg, 256, GEMM_SMEM>>>(Ahi, Alo, Whi, Wlo, bq, Qb);
    // K projection
    convW_kernel<<<cw, 256>>>(Wk, Whi, Wlo);
    splitA_kernel<<<sa, 256>>>(key_in, Ahi, Alo);
    gemm_mma_kernel<<<gg, 256, GEMM_SMEM>>>(Ahi, Alo, Whi, Wlo, bk, Kb);
    // V projection
    convW_kernel<<<cw, 256>>>(Wv, Whi, Wlo);
    splitA_kernel<<<sa, 256>>>(value, Ahi, Alo);
    gemm_mma_kernel<<<gg, 256, GEMM_SMEM>>>(Ahi, Alo, Whi, Wlo, bv, Vb);
    // Attention
    flash_attn_kernel<<<fg, 256, FL_SMEM_BYTES>>>(Qb, Kb, Vb, Cb);
    // Output projection
    convW_kernel<<<cw, 256>>>(Wo, Whi, Wlo);
    splitA_kernel<<<sa, 256>>>(Cb, Ahi, Alo);
    gemm_mma_kernel<<<gg, 256, GEMM_SMEM>>>(Ahi, Alo, Whi, Wlo, bo, out);
}

// round 5
// speedup vs baseline: 2.3734x; 1.9271x over previous
#include <cuda_runtime.h>
#include <cuda_bf16.h>
#include <cstdint>

// Problem constants
#define B_ 2
#define S_ 2048
#define E_ 2048
#define H_ 16
#define D_ 128
#define MROWS (B_ * S_)   // 4096

// ---------------------------------------------------------------------------
// Scratch (no cudaMalloc allowed)
// ---------------------------------------------------------------------------
__device__ float g_Q[(size_t)B_ * S_ * E_];
__device__ float g_K[(size_t)B_ * S_ * E_];
__device__ float g_V[(size_t)B_ * S_ * E_];
__device__ float g_C[(size_t)B_ * S_ * E_];
__device__ __nv_bfloat16 g_Ahi[(size_t)MROWS * E_];   // activations split
__device__ __nv_bfloat16 g_Alo[(size_t)MROWS * E_];
__device__ __nv_bfloat16 g_Whi[(size_t)E_ * E_];      // weights split, transposed [N][K]
__device__ __nv_bfloat16 g_Wlo[(size_t)E_ * E_];

// ---------------------------------------------------------------------------
// Helpers (all legal on base sm_103 target)
// ---------------------------------------------------------------------------
__device__ __forceinline__ uint32_t smem_u32(const void* p) {
    uint32_t a;
    asm("{ .reg .u64 t; cvta.to.shared.u64 t, %1; cvt.u32.u64 %0, t; }"
        : "=r"(a) : "l"(p));
    return a;
}

__device__ __forceinline__ void ldsm_x4(uint32_t* r, uint32_t addr) {
    asm volatile("ldmatrix.sync.aligned.m8n8.x4.shared.b16 {%0,%1,%2,%3}, [%4];"
        : "=r"(r[0]), "=r"(r[1]), "=r"(r[2]), "=r"(r[3]) : "r"(addr));
}
__device__ __forceinline__ void ldsm_x2(uint32_t* r, uint32_t addr) {
    asm volatile("ldmatrix.sync.aligned.m8n8.x2.shared.b16 {%0,%1}, [%2];"
        : "=r"(r[0]), "=r"(r[1]) : "r"(addr));
}
__device__ __forceinline__ void ldsm_x4t(uint32_t* r, uint32_t addr) {
    asm volatile("ldmatrix.sync.aligned.m8n8.x4.trans.shared.b16 {%0,%1,%2,%3}, [%4];"
        : "=r"(r[0]), "=r"(r[1]), "=r"(r[2]), "=r"(r[3]) : "r"(addr));
}

// D += A(16x16 bf16) * B(16x8 bf16), fp32 accum
__device__ __forceinline__ void mma16816(float* c, const uint32_t* a, const uint32_t* b) {
    asm volatile(
        "mma.sync.aligned.m16n8k16.row.col.f32.bf16.bf16.f32 "
        "{%0,%1,%2,%3}, {%4,%5,%6,%7}, {%8,%9}, {%0,%1,%2,%3};"
        : "+f"(c[0]), "+f"(c[1]), "+f"(c[2]), "+f"(c[3])
        : "r"(a[0]), "r"(a[1]), "r"(a[2]), "r"(a[3]), "r"(b[0]), "r"(b[1]));
}

__device__ __forceinline__ float ex2f(float x) {
    float y; asm("ex2.approx.f32 %0, %1;" : "=f"(y) : "f"(x)); return y;
}

// pack two fp32 -> bf16x2 (low = a, high = b)
__device__ __forceinline__ uint32_t packbf(float a, float b) {
    uint32_t r; asm("cvt.rn.bf16x2.f32 %0, %1, %2;" : "=r"(r) : "f"(b), "f"(a));
    return r;
}

// split float4 into hi/lo bf16x2 pairs
__device__ __forceinline__ void split4(float4 v, uint2& hi, uint2& lo) {
    uint32_t h0 = packbf(v.x, v.y), h1 = packbf(v.z, v.w);
    float a0 = __uint_as_float(h0 << 16), a1 = __uint_as_float(h0 & 0xffff0000u);
    float a2 = __uint_as_float(h1 << 16), a3 = __uint_as_float(h1 & 0xffff0000u);
    hi.x = h0; hi.y = h1;
    lo.x = packbf(v.x - a0, v.y - a1);
    lo.y = packbf(v.z - a2, v.w - a3);
}

#define SMEM_SWIZZLE_128B(off) ((off) ^ (((off) >> 3) & 0x70))

// ---------------------------------------------------------------------------
// Split fp32 activations into (hi, lo) bf16, same layout [M][K]
// ---------------------------------------------------------------------------
__global__ void __launch_bounds__(256) splitA_kernel(
    const float* __restrict__ x, __nv_bfloat16* __restrict__ hi,
    __nv_bfloat16* __restrict__ lo)
{
    size_t i = (size_t)blockIdx.x * 256 + threadIdx.x;  // one float4
    float4 v = ((const float4*)x)[i];
    uint2 h, l;
    split4(v, h, l);
    ((uint2*)hi)[i] = h;
    ((uint2*)lo)[i] = l;
}

// ---------------------------------------------------------------------------
// Transpose + split fp32 weights W[K][N] -> hi/lo bf16 [N][K]
// ---------------------------------------------------------------------------
__global__ void __launch_bounds__(256) convW_kernel(
    const float* __restrict__ W, __nv_bfloat16* __restrict__ hi,
    __nv_bfloat16* __restrict__ lo)
{
    __shared__ float t[32][33];
    int tx = threadIdx.x & 31, ty = threadIdx.x >> 5;  // 32 x 8
    int nb = blockIdx.x * 32, kb = blockIdx.y * 32;
    #pragma unroll
    for (int i = 0; i < 4; ++i) {
        int k = kb + ty + i * 8;
        t[ty + i * 8][tx] = W[(size_t)k * E_ + nb + tx];
    }
    __syncthreads();
    #pragma unroll
    for (int i = 0; i < 4; ++i) {
        int n = nb + ty + i * 8;
        float v = t[tx][ty + i * 8];
        __nv_bfloat16 h = __float2bfloat16(v);
        hi[(size_t)n * E_ + kb + tx] = h;
        lo[(size_t)n * E_ + kb + tx] = __float2bfloat16(v - __bfloat162float(h));
    }
}

// ---------------------------------------------------------------------------
// mma.sync split-bf16 GEMM: C[M,N] = A[M,K] * B[N,K]^T + bias  (validated R4)
// ---------------------------------------------------------------------------
#define GEMM_SMEM (4 * 16384)

__global__ void __launch_bounds__(256) gemm_mma_kernel(
    const __nv_bfloat16* __restrict__ Ahi, const __nv_bfloat16* __restrict__ Alo,
    const __nv_bfloat16* __restrict__ Bhi, const __nv_bfloat16* __restrict__ Blo,
    const float* __restrict__ bias, float* __restrict__ C)
{
    extern __shared__ char smc[];
    const uint32_t sb  = smem_u32(smc);
    const uint32_t SAH = sb;
    const uint32_t SAL = sb + 16384;
    const uint32_t SBH = sb + 32768;
    const uint32_t SBL = sb + 49152;

    const int tid  = threadIdx.x;
    const int wid  = tid >> 5;
    const int lane = tid & 31;
    const int bx = blockIdx.x;   // N tile (16)
    const int by = blockIdx.y;   // M tile (32)

    const int warpM = (wid >> 2) * 64;   // 0 or 64
    const int warpN = (wid & 3) * 32;    // 0,32,64,96

    const size_t aRow0 = (size_t)by * 128;
    const size_t bRow0 = (size_t)bx * 128;

    float acc[4][4][4];
    #pragma unroll
    for (int mi = 0; mi < 4; ++mi)
        #pragma unroll
        for (int ni = 0; ni < 4; ++ni)
            #pragma unroll
            for (int j = 0; j < 4; ++j) acc[mi][ni][j] = 0.f;

    const uint32_t aRowL = warpM + (lane & 15);
    const uint32_t aColL = (lane >> 4) * 8;
    const uint32_t bRowL = warpN + (lane & 7);
    const uint32_t bColL = ((lane >> 3) & 1) * 8;

    for (int kc = 0; kc < 32; ++kc) {
        const int k0 = kc * 64;
        __syncthreads();
        #pragma unroll
        for (int it = 0; it < 4; ++it) {
            int idx = tid + it * 256;   // 0..1023
            int r = idx >> 3;
            int s = idx & 7;
            uint32_t off = SMEM_SWIZZLE_128B((uint32_t)(r * 128 + s * 16));
            const uint4* pah = (const uint4*)(Ahi + (aRow0 + r) * E_ + k0);
            const uint4* pal = (const uint4*)(Alo + (aRow0 + r) * E_ + k0);
            const uint4* pbh = (const uint4*)(Bhi + (bRow0 + r) * E_ + k0);
            const uint4* pbl = (const uint4*)(Blo + (bRow0 + r) * E_ + k0);
            *(uint4*)(smc + off)         = pah[s];
            *(uint4*)(smc + 16384 + off) = pal[s];
            *(uint4*)(smc + 32768 + off) = pbh[s];
            *(uint4*)(smc + 49152 + off) = pbl[s];
        }
        __syncthreads();

        #pragma unroll
        for (int ks = 0; ks < 4; ++ks) {
            const uint32_t kb = ks * 16;
            uint32_t ah[4][4], al[4][4], bh[4][2], bl[4][2];
            #pragma unroll
            for (int mi = 0; mi < 4; ++mi) {
                uint32_t off = (aRowL + mi * 16) * 128 + (kb + aColL) * 2;
                off = SMEM_SWIZZLE_128B(off);
                ldsm_x4(ah[mi], SAH + off);
                ldsm_x4(al[mi], SAL + off);
            }
            #pragma unroll
            for (int ni = 0; ni < 4; ++ni) {
                uint32_t off = (bRowL + ni * 8) * 128 + (kb + bColL) * 2;
                off = SMEM_SWIZZLE_128B(off);
                ldsm_x2(bh[ni], SBH + off);
                ldsm_x2(bl[ni], SBL + off);
            }
            #pragma unroll
            for (int mi = 0; mi < 4; ++mi)
                #pragma unroll
                for (int ni = 0; ni < 4; ++ni) {
                    mma16816(acc[mi][ni], ah[mi], bh[ni]);
                    mma16816(acc[mi][ni], ah[mi], bl[ni]);
                    mma16816(acc[mi][ni], al[mi], bh[ni]);
                }
        }
    }

    const int rQuad = lane >> 2;
    const int cPair = (lane & 3) * 2;
    #pragma unroll
    for (int mi = 0; mi < 4; ++mi) {
        #pragma unroll
        for (int ni = 0; ni < 4; ++ni) {
            int row = by * 128 + warpM + mi * 16 + rQuad;
            int col = bx * 128 + warpN + ni * 8 + cPair;
            float b0 = bias[col], b1 = bias[col + 1];
            float2 v0 = make_float2(acc[mi][ni][0] + b0, acc[mi][ni][1] + b1);
            float2 v1 = make_float2(acc[mi][ni][2] + b0, acc[mi][ni][3] + b1);
            *(float2*)(C + (size_t)row * E_ + col)       = v0;
            *(float2*)(C + (size_t)(row + 8) * E_ + col) = v1;
        }
    }
}

// ---------------------------------------------------------------------------
// Tensor-core flash attention, split-bf16 (3-term) for QK^T and PV.
// 128 threads (4 warps x 16 q-rows), BM=64 q rows, kv tiles of 64, D=128.
// Smem: 12 swizzled [64][64] bf16 tiles (8KB each) = 96KB -> 2 CTA/SM.
//   Q hi/lo (d0,d1) | K hi/lo (d0,d1) | V hi/lo (d0,d1)   (V kept [kv][d])
// ---------------------------------------------------------------------------
#define FL_QH 0
#define FL_QL 16384
#define FL_KH 32768
#define FL_KL 49152
#define FL_VH 65536
#define FL_VL 81920
#define FL2_SMEM 98304

__global__ void __launch_bounds__(128) flash_mma_kernel(
    const float* __restrict__ Qg, const float* __restrict__ Kg,
    const float* __restrict__ Vg, float* __restrict__ Ctx)
{
    extern __shared__ char sm[];
    const uint32_t sb = smem_u32(sm);

    const int qt = blockIdx.x, h = blockIdx.y, b = blockIdx.z;
    const int tid = threadIdx.x, w = tid >> 5, lane = tid & 31;
    const float SCALE = 0.08838834764831845f;   // 1/sqrt(128)
    const float L2E = 1.4426950408889634f;

    const float* Qbase = Qg + ((size_t)b * S_ + qt * 64) * E_ + h * D_;

    // Load + scale + split Q into swizzled bf16 tiles (once)
    for (int i = tid; i < 64 * 32; i += 128) {
        int r = i >> 5, c4 = (i & 31) * 4;
        float4 v = *(const float4*)(Qbase + (size_t)r * E_ + c4);
        v.x *= SCALE; v.y *= SCALE; v.z *= SCALE; v.w *= SCALE;
        uint2 hi, lo;
        split4(v, hi, lo);
        uint32_t off = SMEM_SWIZZLE_128B((uint32_t)(r * 128 + (c4 & 63) * 2));
        uint32_t subo = (c4 >> 6) * 8192;
        *(uint2*)(sm + FL_QH + subo + off) = hi;
        *(uint2*)(sm + FL_QL + subo + off) = lo;
    }

    float oacc[16][4];
    #pragma unroll
    for (int f = 0; f < 16; ++f)
        #pragma unroll
        for (int j = 0; j < 4; ++j) oacc[f][j] = 0.f;
    float m0 = -1e30f, m1 = -1e30f, l0 = 0.f, l1 = 0.f;

    const uint32_t aRowL = w * 16 + (lane & 15);
    const uint32_t aColL = (lane >> 4) * 8;
    const uint32_t bRowL = lane & 7;
    const uint32_t bColL = ((lane >> 3) & 1) * 8;
    const uint32_t vR = lane & 7, vM = lane >> 3;  // x4.trans lane addressing

    for (int kt = 0; kt < 32; ++kt) {
        __syncthreads();
        const float* Kb = Kg + ((size_t)b * S_ + kt * 64) * E_ + h * D_;
        const float* Vb = Vg + ((size_t)b * S_ + kt * 64) * E_ + h * D_;
        for (int i = tid; i < 64 * 32; i += 128) {
            int r = i >> 5, c4 = (i & 31) * 4;
            uint32_t off = SMEM_SWIZZLE_128B((uint32_t)(r * 128 + (c4 & 63) * 2));
            uint32_t subo = (c4 >> 6) * 8192;
            float4 kv = *(const float4*)(Kb + (size_t)r * E_ + c4);
            uint2 hi, lo;
            split4(kv, hi, lo);
            *(uint2*)(sm + FL_KH + subo + off) = hi;
            *(uint2*)(sm + FL_KL + subo + off) = lo;
            float4 vv = *(const float4*)(Vb + (size_t)r * E_ + c4);
            split4(vv, hi, lo);
            *(uint2*)(sm + FL_VH + subo + off) = hi;
            *(uint2*)(sm + FL_VL + subo + off) = lo;
        }
        __syncthreads();

        // ---- S = Qs K^T (scaled) : 16x64 per warp, 3-term split ----
        float sacc[8][4];
        #pragma unroll
        for (int ni = 0; ni < 8; ++ni)
            #pragma unroll
            for (int j = 0; j < 4; ++j) sacc[ni][j] = 0.f;

        #pragma unroll
        for (int half = 0; half < 2; ++half) {
            #pragma unroll
            for (int ks = 0; ks < 4; ++ks) {
                const uint32_t kb = ks * 16;
                uint32_t ah[4], al[4];
                uint32_t aoff = SMEM_SWIZZLE_128B(aRowL * 128 + (kb + aColL) * 2);
                ldsm_x4(ah, sb + FL_QH + half * 8192 + aoff);
                ldsm_x4(al, sb + FL_QL + half * 8192 + aoff);
                #pragma unroll
                for (int ni = 0; ni < 8; ++ni) {
                    uint32_t bh[2], bl[2];
                    uint32_t boff = SMEM_SWIZZLE_128B((bRowL + ni * 8) * 128 + (kb + bColL) * 2);
                    ldsm_x2(bh, sb + FL_KH + half * 8192 + boff);
                    ldsm_x2(bl, sb + FL_KL + half * 8192 + boff);
                    mma16816(sacc[ni], ah, bh);
                    mma16816(sacc[ni], ah, bl);
                    mma16816(sacc[ni], al, bh);
                }
            }
        }

        // ---- online softmax in registers (rows rQuad and rQuad+8) ----
        float mx0 = -1e30f, mx1 = -1e30f;
        #pragma unroll
        for (int ni = 0; ni < 8; ++ni) {
            mx0 = fmaxf(mx0, fmaxf(sacc[ni][0], sacc[ni][1]));
            mx1 = fmaxf(mx1, fmaxf(sacc[ni][2], sacc[ni][3]));
        }
        mx0 = fmaxf(mx0, __shfl_xor_sync(0xffffffffu, mx0, 1));
        mx0 = fmaxf(mx0, __shfl_xor_sync(0xffffffffu, mx0, 2));
        mx1 = fmaxf(mx1, __shfl_xor_sync(0xffffffffu, mx1, 1));
        mx1 = fmaxf(mx1, __shfl_xor_sync(0xffffffffu, mx1, 2));
        const float mn0 = fmaxf(m0, mx0), mn1 = fmaxf(m1, mx1);
        const float al0 = ex2f((m0 - mn0) * L2E), al1 = ex2f((m1 - mn1) * L2E);
        m0 = mn0; m1 = mn1;

        uint32_t ph[8][2], pl[8][2];
        float ls0 = 0.f, ls1 = 0.f;
        #pragma unroll
        for (int ni = 0; ni < 8; ++ni) {
            float p00 = ex2f((sacc[ni][0] - mn0) * L2E);
            float p01 = ex2f((sacc[ni][1] - mn0) * L2E);
            float p10 = ex2f((sacc[ni][2] - mn1) * L2E);
            float p11 = ex2f((sacc[ni][3] - mn1) * L2E);
            ls0 += p00 + p01;
            ls1 += p10 + p11;
            uint32_t hp0 = packbf(p00, p01);
            uint32_t hp1 = packbf(p10, p11);
            float h00 = __uint_as_float(hp0 << 16);
            float h01 = __uint_as_float(hp0 & 0xffff0000u);
            float h10 = __uint_as_float(hp1 << 16);
            float h11 = __uint_as_float(hp1 & 0xffff0000u);
            ph[ni][0] = hp0;
            ph[ni][1] = hp1;
            pl[ni][0] = packbf(p00 - h00, p01 - h01);
            pl[ni][1] = packbf(p10 - h10, p11 - h11);
        }
        ls0 += __shfl_xor_sync(0xffffffffu, ls0, 1);
        ls0 += __shfl_xor_sync(0xffffffffu, ls0, 2);
        ls1 += __shfl_xor_sync(0xffffffffu, ls1, 1);
        ls1 += __shfl_xor_sync(0xffffffffu, ls1, 2);
        l0 = l0 * al0 + ls0;
        l1 = l1 * al1 + ls1;

        #pragma unroll
        for (int f = 0; f < 16; ++f) {
            oacc[f][0] *= al0; oacc[f][1] *= al0;
            oacc[f][2] *= al1; oacc[f][3] *= al1;
        }

        // ---- O += P V : 16x128 per warp, 3-term split ----
        #pragma unroll
        for (int kf = 0; kf < 4; ++kf) {
            uint32_t aPh[4] = { ph[2*kf][0], ph[2*kf][1], ph[2*kf+1][0], ph[2*kf+1][1] };
            uint32_t aPl[4] = { pl[2*kf][0], pl[2*kf][1], pl[2*kf+1][0], pl[2*kf+1][1] };
            #pragma unroll
            for (int nd = 0; nd < 8; ++nd) {
                const uint32_t sub = (nd >> 2) * 8192;
                const uint32_t dd = (nd & 3) * 16;
                const uint32_t kvr = kf * 16 + (vM & 1) * 8 + vR;
                const uint32_t dc = dd + (vM >> 1) * 8;
                const uint32_t voff = SMEM_SWIZZLE_128B(kvr * 128 + dc * 2);
                uint32_t bh4[4], bl4[4];
                ldsm_x4t(bh4, sb + FL_VH + sub + voff);
                ldsm_x4t(bl4, sb + FL_VL + sub + voff);
                mma16816(oacc[2*nd],     aPh, bh4);
                mma16816(oacc[2*nd],     aPh, bl4);
                mma16816(oacc[2*nd],     aPl, bh4);
                mma16816(oacc[2*nd + 1], aPh, bh4 + 2);
                mma16816(oacc[2*nd + 1], aPh, bl4 + 2);
                mma16816(oacc[2*nd + 1], aPl, bh4 + 2);
            }
        }
    }

    // ---- finalize ----
    const float inv0 = 1.f / l0, inv1 = 1.f / l1;
    const int rQuad = lane >> 2, cPair = (lane & 3) * 2;
    float* op = Ctx + ((size_t)b * S_ + qt * 64 + w * 16 + rQuad) * E_ + h * D_;
    #pragma unroll
    for (int f = 0; f < 16; ++f) {
        int d = f * 8 + cPair;
        *(float2*)(op + d) = make_float2(oacc[f][0] * inv0, oacc[f][1] * inv0);
        *(float2*)(op + 8 * E_ + d) = make_float2(oacc[f][2] * inv1, oacc[f][3] * inv1);
    }
}

// ---------------------------------------------------------------------------
extern "C" void kernel_launch(void* const* d_in, const int* in_sizes, int n_in,
                              void* d_out, int out_size)
{
    const float* query  = (const float*)d_in[0];
    const float* key_in = (const float*)d_in[1];
    const float* value  = (const float*)d_in[2];
    const float* Wq = (const float*)d_in[3];
    const float* bq = (const float*)d_in[4];
    const float* Wk = (const float*)d_in[5];
    const float* bk = (const float*)d_in[6];
    const float* Wv = (const float*)d_in[7];
    const float* bv = (const float*)d_in[8];
    const float* Wo = (const float*)d_in[9];
    const float* bo = (const float*)d_in[10];
    float* out = (float*)d_out;

    float *Qb, *Kb, *Vb, *Cb;
    __nv_bfloat16 *Ahi, *Alo, *Whi, *Wlo;
    cudaGetSymbolAddress((void**)&Qb, g_Q);
    cudaGetSymbolAddress((void**)&Kb, g_K);
    cudaGetSymbolAddress((void**)&Vb, g_V);
    cudaGetSymbolAddress((void**)&Cb, g_C);
    cudaGetSymbolAddress((void**)&Ahi, g_Ahi);
    cudaGetSymbolAddress((void**)&Alo, g_Alo);
    cudaGetSymbolAddress((void**)&Whi, g_Whi);
    cudaGetSymbolAddress((void**)&Wlo, g_Wlo);

    cudaFuncSetAttribute(flash_mma_kernel,
                         cudaFuncAttributeMaxDynamicSharedMemorySize,
                         FL2_SMEM);
    cudaFuncSetAttribute(gemm_mma_kernel,
                         cudaFuncAttributeMaxDynamicSharedMemorySize,
                         GEMM_SMEM);

    const dim3 cw(E_ / 32, E_ / 32);            // convW tiles
    const int  sa = (MROWS * E_ / 4) / 256;     // splitA blocks (8192)
    const dim3 gg(E_ / 128, MROWS / 128);       // gemm tiles (16, 32)
    const dim3 fg(S_ / 64, H_, B_);             // flash (32, 16, 2)

    // Q projection
    convW_kernel<<<cw, 256>>>(Wq, Whi, Wlo);
    splitA_kernel<<<sa, 256>>>(query, Ahi, Alo);
    gemm_mma_kernel<<<gg, 256, GEMM_SMEM>>>(Ahi, Alo, Whi, Wlo, bq, Qb);
    // K projection
    convW_kernel<<<cw, 256>>>(Wk, Whi, Wlo);
    splitA_kernel<<<sa, 256>>>(key_in, Ahi, Alo);
    gemm_mma_kernel<<<gg, 256, GEMM_SMEM>>>(Ahi, Alo, Whi, Wlo, bk, Kb);
    // V projection
    convW_kernel<<<cw, 256>>>(Wv, Whi, Wlo);
    splitA_kernel<<<sa, 256>>>(value, Ahi, Alo);
    gemm_mma_kernel<<<gg, 256, GEMM_SMEM>>>(Ahi, Alo, Whi, Wlo, bv, Vb);
    // Attention (tensor-core flash)
    flash_mma_kernel<<<fg, 128, FL2_SMEM>>>(Qb, Kb, Vb, Cb);
    // Output projection
    convW_kernel<<<cw, 256>>>(Wo, Whi, Wlo);
    splitA_kernel<<<sa, 256>>>(Cb, Ahi, Alo);
    gemm_mma_kernel<<<gg, 256, GEMM_SMEM>>>(Ahi, Alo, Whi, Wlo, bo, out);
}